// round 8
// baseline (speedup 1.0000x reference)
#include <cuda_runtime.h>

typedef unsigned long long ull;

#define IMG_W 512
#define IMG_H 512
#define NPLANES 48            // 16 batch * 3 channels
#define NSTRIPS 6             // strips per plane
#define STRIP_ROWS 88         // 22 chunks of 4 rows (rows >= 512 masked)
#define NBLOCKS (NPLANES * NSTRIPS)   // 288 blocks, occ=2 -> one wave
#define NTHREADS 256
#define ROWU 256              // float2 elements per 512-px image row
#define NCHUNKS 22
#define CROWS 4               // output rows per chunk

#define NFIELDS 4             // x, y, u=x^2+y^2, v=x*y
#define ROWF 528              // floats per V row: 8 left halo + 512 + 8 right halo
#define BUF_FLOATS (NFIELDS * CROWS * ROWF)    // 8448
#define SMEM_BYTES (2 * BUF_FLOATS * 4)        // 67584 -> 2 blocks/SM fit

#define SSIM_C1 0.0001f
#define SSIM_C2 0.0009f

// 1D gaussian (sigma=1.5, 11 taps, normalized) as literals -> FFMA-imm (rt=1)
#define G0 0.00102836f
#define G1 0.00759863f
#define G2 0.03600078f
#define G3 0.10936075f
#define G4 0.21300559f
#define G5 0.26601179f

__device__ double g_partials[NBLOCKS];
__device__ unsigned g_arrive = 0;

__device__ __forceinline__ ull pack2(float x, float y) {
    ull r; asm("mov.b64 %0, {%1,%2};" : "=l"(r) : "f"(x), "f"(y)); return r;
}
__device__ __forceinline__ ull mul2(ull a, ull b) {
    ull d; asm("mul.rn.f32x2 %0, %1, %2;" : "=l"(d) : "l"(a), "l"(b)); return d;
}
__device__ __forceinline__ ull fma2(ull a, ull b, ull c) {
    ull d; asm("fma.rn.f32x2 %0, %1, %2, %3;" : "=l"(d) : "l"(a), "l"(b), "l"(c)); return d;
}

// Horizontal 11-tap conv for 4 px (cols 4g..4g+3) from a V row.
// rp = row base + 4g floats (16B aligned; lanes stride 16B -> conflict-free LDS.128)
__device__ __forceinline__ void hconv4(const float* __restrict__ rp, float o[4]) {
    float e[20];
    const float4* q = (const float4*)rp;
#pragma unroll
    for (int i = 0; i < 5; ++i) {
        float4 v = q[i];
        e[4 * i] = v.x; e[4 * i + 1] = v.y; e[4 * i + 2] = v.z; e[4 * i + 3] = v.w;
    }
#pragma unroll
    for (int p = 0; p < 4; ++p) {
        float a = G0 * e[p + 3];
        a = fmaf(G1, e[p + 4], a);  a = fmaf(G2, e[p + 5], a);
        a = fmaf(G3, e[p + 6], a);  a = fmaf(G4, e[p + 7], a);
        a = fmaf(G5, e[p + 8], a);  a = fmaf(G4, e[p + 9], a);
        a = fmaf(G3, e[p + 10], a); a = fmaf(G2, e[p + 11], a);
        a = fmaf(G1, e[p + 12], a); a = fmaf(G0, e[p + 13], a);
        o[p] = a;
    }
}

// SSIM from the 4 convolved fields: mu1, mu2, euu=E[x^2+y^2], exy=E[xy]
__device__ __forceinline__ float ssim_px(float mu1, float mu2, float euu, float exy) {
    float msq = mu1 * mu1;
    msq = fmaf(mu2, mu2, msq);           // mu1^2 + mu2^2
    float m12 = mu1 * mu2;
    float ssum = euu - msq;              // sig1^2 + sig2^2
    float s12  = exy - m12;
    float num = fmaf(2.0f, m12, SSIM_C1) * fmaf(2.0f, s12, SSIM_C2);
    float den = (msq + SSIM_C1) * (ssum + SSIM_C2);
    return __fdividef(num, den);
}

__global__ void __launch_bounds__(NTHREADS, 2)
ssim_main(const float* __restrict__ img1, const float* __restrict__ img2,
          float* __restrict__ out) {
    extern __shared__ float Vs[];
    __shared__ float wsums[NTHREADS / 32];
    __shared__ int is_last;

    const int bx = blockIdx.x;
    const int plane = bx / NSTRIPS;
    const int strip = bx - plane * NSTRIPS;
    const int r0 = strip * STRIP_ROWS;
    const int t = threadIdx.x;

    // Zero halos in BOTH buffers: per (field,row), floats [0..7] and [520..527]
    for (int idx = t; idx < 2 * NFIELDS * CROWS * 16; idx += NTHREADS) {
        int fr = idx >> 4, e = idx & 15;
        Vs[fr * ROWF + ((e < 8) ? e : (512 + e))] = 0.0f;
    }

    const ull* __restrict__ p1 = (const ull*)img1 + (size_t)plane * (IMG_H * ROWU) + t;
    const ull* __restrict__ p2 = (const ull*)img2 + (size_t)plane * (IMG_H * ROWU) + t;

    const ull Wp[6] = {pack2(G0, G0), pack2(G1, G1), pack2(G2, G2),
                       pack2(G3, G3), pack2(G4, G4), pack2(G5, G5)};

    auto loadrow = [&](int row, ull& a, ull& b) {
        if ((unsigned)row < IMG_H) {
            a = p1[(size_t)row * ROWU];
            b = p2[(size_t)row * ROWU];
        } else { a = 0ull; b = 0ull; }
    };

    // Vertical scatter for the chunk whose first output row is Rv -> acc
    auto vconv = [&](int Rv, ull acc[NFIELDS][CROWS]) {
#pragma unroll
        for (int f = 0; f < NFIELDS; ++f)
#pragma unroll
            for (int j = 0; j < CROWS; ++j) acc[f][j] = 0ull;
        ull a, b;
        loadrow(Rv - 5, a, b);
#pragma unroll
        for (int i = 0; i < CROWS + 10; ++i) {
            const ull pa = a, pb = b;            // input row Rv-5+i
            if (i < CROWS + 9) loadrow(Rv - 4 + i, a, b);
            const ull pu = fma2(pa, pa, mul2(pb, pb));
            const ull pv = mul2(pa, pb);
            const int jlo = (i - 10 > 0) ? (i - 10) : 0;
            const int jhi = (i < CROWS - 1) ? i : (CROWS - 1);
#pragma unroll
            for (int j = jlo; j <= jhi; ++j) {
                const int k = i - j;                    // 0..10
                const int wi = (k < 6) ? k : 10 - k;    // symmetric weight
                acc[0][j] = fma2(pa, Wp[wi], acc[0][j]);
                acc[1][j] = fma2(pb, Wp[wi], acc[1][j]);
                acc[2][j] = fma2(pu, Wp[wi], acc[2][j]);
                acc[3][j] = fma2(pv, Wp[wi], acc[3][j]);
            }
        }
    };

    auto store_acc = [&](float* sbuf, ull acc[NFIELDS][CROWS]) {
#pragma unroll
        for (int j = 0; j < CROWS; ++j) {
            const int off = j * ROWF + 8 + 2 * t;
#pragma unroll
            for (int f = 0; f < NFIELDS; ++f)
                *(ull*)(sbuf + f * CROWS * ROWF + off) = acc[f][j];
        }
    };

    float accv = 0.0f;

    // Prologue: chunk 0 -> buffer 0
    {
        ull acc[NFIELDS][CROWS];
        vconv(r0, acc);
        store_acc(Vs, acc);
    }
    __syncthreads();   // buffer 0 + halo zeros visible

    for (int c = 0; c < NCHUNKS; ++c) {
        const int Rh = r0 + c * CROWS;       // chunk being consumed (horizontal)
        const bool do_v = (c + 1 < NCHUNKS);

        // ---- Vertical compute for chunk c+1 (FMA + LDG stream) ----
        ull acc[NFIELDS][CROWS];
        if (do_v) vconv(Rh + CROWS, acc);

        // ---- Horizontal + SSIM for chunk c (LDS + FMA stream) ----
        // Same inter-barrier region as the vertical above -> pipes overlap.
        const float* sbufc = Vs + (c & 1) * BUF_FLOATS;
#pragma unroll
        for (int rd = 0; rd < 2; ++rd) {
            const int job = t + rd * NTHREADS;
            const int row = job >> 7;        // 0..3
            const int g = job & 127;
            const float* base = sbufc + row * ROWF + 4 * g;
            float m1[4], m2[4], uu[4], vv[4];
            hconv4(base + 0 * CROWS * ROWF, m1);
            hconv4(base + 1 * CROWS * ROWF, m2);
            hconv4(base + 2 * CROWS * ROWF, uu);
            hconv4(base + 3 * CROWS * ROWF, vv);
            if (Rh + row < IMG_H) {
#pragma unroll
                for (int p = 0; p < 4; ++p)
                    accv += ssim_px(m1[p], m2[p], uu[p], vv[p]);
            }
        }

        // ---- Store chunk c+1 after the LDS burst, then one barrier ----
        if (do_v) store_acc(Vs + ((c + 1) & 1) * BUF_FLOATS, acc);
        __syncthreads();
    }

    // ---- Deterministic block reduction ----
#pragma unroll
    for (int off = 16; off; off >>= 1)
        accv += __shfl_xor_sync(0xffffffffu, accv, off);
    if ((t & 31) == 0) wsums[t >> 5] = accv;
    __syncthreads();
    if (t == 0) {
        float s = 0.0f;
#pragma unroll
        for (int i = 0; i < NTHREADS / 32; ++i) s += wsums[i];
        g_partials[bx] = (double)s;
        __threadfence();
        unsigned old = atomicAdd(&g_arrive, 1u);
        is_last = (old == NBLOCKS - 1) ? 1 : 0;
    }
    __syncthreads();

    // ---- Fused deterministic finalize (last-arriving block, warp 0) ----
    if (is_last && t < 32) {
        __threadfence();
        double s = 0.0;
#pragma unroll
        for (int k = 0; k < NBLOCKS / 32; ++k) s += g_partials[t + 32 * k];
#pragma unroll
        for (int off = 16; off; off >>= 1)
            s += __shfl_xor_sync(0xffffffffu, s, off);
        if (t == 0) {
            out[0] = (float)(1.0 - s / 12582912.0);   // 16*3*512*512
            g_arrive = 0;   // reset for next graph replay
        }
    }
}

extern "C" void kernel_launch(void* const* d_in, const int* in_sizes, int n_in,
                              void* d_out, int out_size) {
    const float* img1 = (const float*)d_in[0];
    const float* img2 = (const float*)d_in[1];
    // d_in[2] (gaussian window) is deterministic; weights baked in as immediates.
    cudaFuncSetAttribute(ssim_main, cudaFuncAttributeMaxDynamicSharedMemorySize,
                         SMEM_BYTES);
    ssim_main<<<NBLOCKS, NTHREADS, SMEM_BYTES>>>(img1, img2, (float*)d_out);
}

// round 9
// speedup vs baseline: 1.1659x; 1.1659x over previous
#include <cuda_runtime.h>

typedef unsigned long long ull;

#define IMG_W 512
#define IMG_H 512
#define NPLANES 48            // 16 batch * 3 channels
#define NSTRIPS 12            // strips per plane
#define STRIP_ROWS 44         // 11 chunks of 4 rows (rows >= 512 masked)
#define NBLOCKS (NPLANES * NSTRIPS)   // 576 blocks, occ=4 -> one wave (<=592)
#define NTHREADS 128          // each thread owns 4 adjacent columns
#define ROWQ 128              // ulonglong2 (4 floats) per 512-px image row
#define NCHUNKS 11
#define CROWS 4               // output rows per chunk

#define NFIELDS 4             // x, y, u=x^2+y^2, v=x*y
#define ROWF 528              // floats per V row: 8 left halo + 512 + 8 right halo
#define SMEM_FLOATS (NFIELDS * CROWS * ROWF)
#define SMEM_BYTES (SMEM_FLOATS * 4)   // 33792 -> 4 blocks/SM fit

#define SSIM_C1 0.0001f
#define SSIM_C2 0.0009f

// 1D gaussian (sigma=1.5, 11 taps, normalized) as literals -> FFMA-imm (rt=1)
#define G0 0.00102836f
#define G1 0.00759863f
#define G2 0.03600078f
#define G3 0.10936075f
#define G4 0.21300559f
#define G5 0.26601179f

__device__ double g_partials[NBLOCKS];
__device__ unsigned g_arrive = 0;

__device__ __forceinline__ ull pack2(float x, float y) {
    ull r; asm("mov.b64 %0, {%1,%2};" : "=l"(r) : "f"(x), "f"(y)); return r;
}
__device__ __forceinline__ ull mul2(ull a, ull b) {
    ull d; asm("mul.rn.f32x2 %0, %1, %2;" : "=l"(d) : "l"(a), "l"(b)); return d;
}
__device__ __forceinline__ ull fma2(ull a, ull b, ull c) {
    ull d; asm("fma.rn.f32x2 %0, %1, %2, %3;" : "=l"(d) : "l"(a), "l"(b), "l"(c)); return d;
}

// Horizontal 11-tap conv for 4 px (cols 4g..4g+3) from a V row.
// rp = row base + 4g floats (16B aligned; lanes stride 16B -> conflict-free LDS.128)
__device__ __forceinline__ void hconv4(const float* __restrict__ rp, float o[4]) {
    float e[20];
    const float4* q = (const float4*)rp;
#pragma unroll
    for (int i = 0; i < 5; ++i) {
        float4 v = q[i];
        e[4 * i] = v.x; e[4 * i + 1] = v.y; e[4 * i + 2] = v.z; e[4 * i + 3] = v.w;
    }
#pragma unroll
    for (int p = 0; p < 4; ++p) {
        float a = G0 * e[p + 3];
        a = fmaf(G1, e[p + 4], a);  a = fmaf(G2, e[p + 5], a);
        a = fmaf(G3, e[p + 6], a);  a = fmaf(G4, e[p + 7], a);
        a = fmaf(G5, e[p + 8], a);  a = fmaf(G4, e[p + 9], a);
        a = fmaf(G3, e[p + 10], a); a = fmaf(G2, e[p + 11], a);
        a = fmaf(G1, e[p + 12], a); a = fmaf(G0, e[p + 13], a);
        o[p] = a;
    }
}

// SSIM from the 4 convolved fields: mu1, mu2, euu=E[x^2+y^2], exy=E[xy]
__device__ __forceinline__ float ssim_px(float mu1, float mu2, float euu, float exy) {
    float msq = mu1 * mu1;
    msq = fmaf(mu2, mu2, msq);           // mu1^2 + mu2^2
    float m12 = mu1 * mu2;
    float ssum = euu - msq;              // sig1^2 + sig2^2
    float s12  = exy - m12;
    float num = fmaf(2.0f, m12, SSIM_C1) * fmaf(2.0f, s12, SSIM_C2);
    float den = (msq + SSIM_C1) * (ssum + SSIM_C2);
    return __fdividef(num, den);
}

__global__ void __launch_bounds__(NTHREADS, 4)
ssim_main(const float* __restrict__ img1, const float* __restrict__ img2,
          float* __restrict__ out) {
    extern __shared__ float Vs[];
    __shared__ float wsums[NTHREADS / 32];
    __shared__ int is_last;

    const int bx = blockIdx.x;
    const int plane = bx / NSTRIPS;
    const int strip = bx - plane * NSTRIPS;
    const int r0 = strip * STRIP_ROWS;
    const int t = threadIdx.x;

    // Zero halos: per (field,row), floats [0..7] and [520..527]
    for (int idx = t; idx < NFIELDS * CROWS * 16; idx += NTHREADS) {
        int fr = idx >> 4, e = idx & 15;
        Vs[fr * ROWF + ((e < 8) ? e : (512 + e))] = 0.0f;
    }

    // Thread t owns cols 4t..4t+3 -> one ulonglong2 (two f32x2 lanes) per image row
    const ulonglong2* __restrict__ p1 =
        (const ulonglong2*)img1 + (size_t)plane * (IMG_H * ROWQ) + t;
    const ulonglong2* __restrict__ p2 =
        (const ulonglong2*)img2 + (size_t)plane * (IMG_H * ROWQ) + t;

    const ull Wp[6] = {pack2(G0, G0), pack2(G1, G1), pack2(G2, G2),
                       pack2(G3, G3), pack2(G4, G4), pack2(G5, G5)};

    auto loadrow = [&](int row, ulonglong2& A, ulonglong2& B) {
        if ((unsigned)row < IMG_H) {
            A = p1[(size_t)row * ROWQ];
            B = p2[(size_t)row * ROWQ];
        } else { A.x = A.y = B.x = B.y = 0ull; }
    };

    float accv = 0.0f;

    ulonglong2 A, B;
    loadrow(r0 - 5, A, B);   // prefetch first input row

    __syncthreads();         // halo zeros visible

    for (int c = 0; c < NCHUNKS; ++c) {
        const int R = r0 + c * CROWS;    // first output row of this chunk

        // ---- Vertical scatter: 14 input rows -> 4 output accumulators,
        //      two f32x2 column streams per thread ----
        ull acc[NFIELDS][CROWS][2];
#pragma unroll
        for (int f = 0; f < NFIELDS; ++f)
#pragma unroll
            for (int j = 0; j < CROWS; ++j) { acc[f][j][0] = 0ull; acc[f][j][1] = 0ull; }

#pragma unroll
        for (int i = 0; i < CROWS + 10; ++i) {
            const ulonglong2 PA = A, PB = B;     // input row R-5+i
            // Prefetch next row (i==13 prefetches next chunk's first row R-1)
            {
                const int nrow = (i < CROWS + 9) ? (R - 4 + i) : (R - 1);
                loadrow(nrow, A, B);
            }

            const ull pu0 = fma2(PA.x, PA.x, mul2(PB.x, PB.x));
            const ull pv0 = mul2(PA.x, PB.x);
            const ull pu1 = fma2(PA.y, PA.y, mul2(PB.y, PB.y));
            const ull pv1 = mul2(PA.y, PB.y);

            const int jlo = (i - 10 > 0) ? (i - 10) : 0;
            const int jhi = (i < CROWS - 1) ? i : (CROWS - 1);
#pragma unroll
            for (int j = jlo; j <= jhi; ++j) {
                const int k = i - j;                    // 0..10
                const int wi = (k < 6) ? k : 10 - k;    // symmetric weight
                acc[0][j][0] = fma2(PA.x, Wp[wi], acc[0][j][0]);
                acc[0][j][1] = fma2(PA.y, Wp[wi], acc[0][j][1]);
                acc[1][j][0] = fma2(PB.x, Wp[wi], acc[1][j][0]);
                acc[1][j][1] = fma2(PB.y, Wp[wi], acc[1][j][1]);
                acc[2][j][0] = fma2(pu0, Wp[wi], acc[2][j][0]);
                acc[2][j][1] = fma2(pu1, Wp[wi], acc[2][j][1]);
                acc[3][j][0] = fma2(pv0, Wp[wi], acc[3][j][0]);
                acc[3][j][1] = fma2(pv1, Wp[wi], acc[3][j][1]);
            }
        }

        // Store V rows to shared (16B-aligned STS.128, conflict-free)
#pragma unroll
        for (int j = 0; j < CROWS; ++j) {
            const int off = j * ROWF + 8 + 4 * t;    // byte 32 + 16t -> 16B aligned
#pragma unroll
            for (int f = 0; f < NFIELDS; ++f) {
                ulonglong2 v; v.x = acc[f][j][0]; v.y = acc[f][j][1];
                *(ulonglong2*)(Vs + f * CROWS * ROWF + off) = v;
            }
        }

        __syncthreads();   // V rows visible

        // ---- Horizontal + SSIM: 4 rows x 128 groups of 4 px = 512 jobs ----
#pragma unroll
        for (int rd = 0; rd < 4; ++rd) {
            const int job = t + rd * NTHREADS;
            const int row = job >> 7;      // 0..3
            const int g = job & 127;
            const float* base = Vs + row * ROWF + 4 * g;
            float m1[4], m2[4], uu[4], vv[4];
            hconv4(base + 0 * CROWS * ROWF, m1);
            hconv4(base + 1 * CROWS * ROWF, m2);
            hconv4(base + 2 * CROWS * ROWF, uu);
            hconv4(base + 3 * CROWS * ROWF, vv);
            if (R + row < IMG_H) {
#pragma unroll
                for (int p = 0; p < 4; ++p)
                    accv += ssim_px(m1[p], m2[p], uu[p], vv[p]);
            }
        }
        __syncthreads();   // horizontal reads done before next chunk's STS
    }

    // ---- Deterministic block reduction ----
#pragma unroll
    for (int off = 16; off; off >>= 1)
        accv += __shfl_xor_sync(0xffffffffu, accv, off);
    if ((t & 31) == 0) wsums[t >> 5] = accv;
    __syncthreads();
    if (t == 0) {
        float s = 0.0f;
#pragma unroll
        for (int i = 0; i < NTHREADS / 32; ++i) s += wsums[i];
        g_partials[bx] = (double)s;
        __threadfence();
        unsigned old = atomicAdd(&g_arrive, 1u);
        is_last = (old == NBLOCKS - 1) ? 1 : 0;
    }
    __syncthreads();

    // ---- Fused deterministic finalize (last-arriving block, warp 0) ----
    if (is_last && t < 32) {
        __threadfence();
        double s = 0.0;
#pragma unroll
        for (int k = 0; k < NBLOCKS / 32; ++k) s += g_partials[t + 32 * k];
#pragma unroll
        for (int off = 16; off; off >>= 1)
            s += __shfl_xor_sync(0xffffffffu, s, off);
        if (t == 0) {
            out[0] = (float)(1.0 - s / 12582912.0);   // 16*3*512*512
            g_arrive = 0;   // reset for next graph replay
        }
    }
}

extern "C" void kernel_launch(void* const* d_in, const int* in_sizes, int n_in,
                              void* d_out, int out_size) {
    const float* img1 = (const float*)d_in[0];
    const float* img2 = (const float*)d_in[1];
    // d_in[2] (gaussian window) is deterministic; weights baked in as immediates.
    cudaFuncSetAttribute(ssim_main, cudaFuncAttributeMaxDynamicSharedMemorySize,
                         SMEM_BYTES);
    ssim_main<<<NBLOCKS, NTHREADS, SMEM_BYTES>>>(img1, img2, (float*)d_out);
}